// round 2
// baseline (speedup 1.0000x reference)
#include <cuda_runtime.h>
#include <math.h>

// Input order (metadata):
// 0 pred_Rot1  [BS,3]        f32
// 1 pred_Rot2  [BS,3]        f32
// 2 pred_Recon [BS,N_PTS,3]  f32
// 3 pred_Tran  [BS,3]        f32
// 4 pred_Size  [BS,3]        f32
// 5 gt_Rotation[BS,3,3]      f32
// 6 gt_Recon   [BS,N_PTS,3]  f32
// 7 gt_Tran    [BS,3]        f32
// 8 gt_Size    [BS,3]        f32
// 9 sym        [BS,6]        i32
// out: 5 f32  [8*rot1, 8*rot2, 8*recon, 8*tran, 8*size]

#define BASE 12
#define RBLK_MAX 1184                  // up to 8 waves of 148 SMs
#define RTHR 256

__device__ float g_partials[RBLK_MAX];

// ---------------------------------------------------------------------------
// Kernel 1: streaming L1 reduction over the recon tensors (HBM-bound).
// Deterministic: fixed grid per launch config, per-block tree reduction,
// no atomics. n4 = number of float4 elements; tail handles n%4 scalars.
// ---------------------------------------------------------------------------
__global__ void __launch_bounds__(RTHR, 4)
recon_reduce_kernel(const float* __restrict__ pf, const float* __restrict__ gf,
                    int n4, int ntail, int nblocks) {
    const float4* __restrict__ p = (const float4*)pf;
    const float4* __restrict__ g = (const float4*)gf;
    float acc = 0.0f;
    int idx = blockIdx.x * RTHR + threadIdx.x;
    const int stride = nblocks * RTHR;
    #pragma unroll 4
    for (int i = idx; i < n4; i += stride) {
        float4 a = __ldg(&p[i]);
        float4 b = __ldg(&g[i]);
        acc += fabsf(a.x - b.x) + fabsf(a.y - b.y)
             + fabsf(a.z - b.z) + fabsf(a.w - b.w);
    }
    // tail scalars (n not divisible by 4) — handled by first few threads of blk0
    if (blockIdx.x == 0 && threadIdx.x < ntail) {
        int base = n4 * 4 + threadIdx.x;
        acc += fabsf(pf[base] - gf[base]);
    }
    __shared__ float sh[RTHR];
    sh[threadIdx.x] = acc;
    __syncthreads();
    #pragma unroll
    for (int s = RTHR / 2; s > 0; s >>= 1) {
        if (threadIdx.x < s) sh[threadIdx.x] += sh[threadIdx.x + s];
        __syncthreads();
    }
    if (threadIdx.x == 0) g_partials[blockIdx.x] = sh[0];
}

// ---------------------------------------------------------------------------
// Kernel 2: one block of 128 threads. Thread t strides over batch rows for
// the small losses; everyone cooperates reducing the recon partials.
// ---------------------------------------------------------------------------
#define FTHR 128

__device__ __forceinline__ float block_reduce(float v, float* sh) {
    int t = threadIdx.x;
    sh[t] = v;
    __syncthreads();
    #pragma unroll
    for (int s = FTHR / 2; s > 0; s >>= 1) {
        if (t < s) sh[t] += sh[t + s];
        __syncthreads();
    }
    float r = sh[0];
    __syncthreads();
    return r;
}

__global__ void __launch_bounds__(FTHR)
finalize_kernel(const float* __restrict__ pR1, const float* __restrict__ pR2,
                const float* __restrict__ pT,  const float* __restrict__ pS,
                const float* __restrict__ gR,  const float* __restrict__ gT,
                const float* __restrict__ gS,  const int* __restrict__ sym,
                float* __restrict__ out, int bs, int n_recon_elems,
                int n_partials) {
    const int t = threadIdx.x;
    __shared__ float sh[FTHR];

    // ---- recon: reduce the partials written by kernel 1 ----
    float rsum = 0.0f;
    for (int i = t; i < n_partials; i += FTHR) rsum += g_partials[i];
    float recon_total = block_reduce(rsum, sh);

    // ---- per-batch small losses (strided in case bs > FTHR) ----
    float rot1_b = 0.0f, rot2num_b = 0.0f, mask_b = 0.0f;
    float tran_b = 0.0f, size_b = 0.0f;
    for (int b = t; b < bs; b += FTHR) {
        const float* R = gR + b * 9;   // row-major R[i*3+j]
        float c0x = R[0], c0y = R[3], c0z = R[6];   // column 0
        float c1x = R[1], c1y = R[4], c1z = R[7];   // column 1
        float c2x = R[2], c2y = R[5], c2z = R[8];   // column 2

        // Rot1: candidates R[:,1] and -R[:,1]
        float p0 = pR1[b * 3 + 0], p1 = pR1[b * 3 + 1], p2 = pR1[b * 3 + 2];
        float l1a = (fabsf(p0 - c1x) + fabsf(p1 - c1y) + fabsf(p2 - c1z)) * (1.0f / 3.0f);
        float l1b = (fabsf(p0 + c1x) + fabsf(p1 + c1y) + fabsf(p2 + c1z)) * (1.0f / 3.0f);
        rot1_b += (sym[b * 6 + 2] == 1) ? fminf(l1a, l1b) : l1a;

        // Rot2: v_k = cos(t)*R[:,0] - sin(t)*R[:,2], min over BASE rotations
        float q0 = pR2[b * 3 + 0], q1 = pR2[b * 3 + 1], q2 = pR2[b * 3 + 2];
        float l2min = 3.4e38f;
        #pragma unroll
        for (int k = 0; k < BASE; k++) {
            float th = (float)k * (6.283185307179586f / (float)BASE);
            float c = cosf(th), s = sinf(th);
            float vx = c * c0x - s * c2x;
            float vy = c * c0y - s * c2y;
            float vz = c * c0z - s * c2z;
            float l = (fabsf(q0 - vx) + fabsf(q1 - vy) + fabsf(q2 - vz)) * (1.0f / 3.0f);
            l2min = fminf(l2min, l);
        }
        float m = (sym[b * 6 + 0] == 0) ? 1.0f : 0.0f;
        mask_b += m;
        rot2num_b += l2min * m;

        tran_b += fabsf(pT[b * 3 + 0] - gT[b * 3 + 0])
                + fabsf(pT[b * 3 + 1] - gT[b * 3 + 1])
                + fabsf(pT[b * 3 + 2] - gT[b * 3 + 2]);
        size_b += fabsf(pS[b * 3 + 0] - gS[b * 3 + 0])
                + fabsf(pS[b * 3 + 1] - gS[b * 3 + 1])
                + fabsf(pS[b * 3 + 2] - gS[b * 3 + 2]);
    }

    float rot1_sum = block_reduce(rot1_b, sh);
    float rot2_sum = block_reduce(rot2num_b, sh);
    float mask_sum = block_reduce(mask_b, sh);
    float tran_sum = block_reduce(tran_b, sh);
    float size_sum = block_reduce(size_b, sh);

    if (t == 0) {
        float rot1 = rot1_sum / (float)bs;
        float rot2 = (mask_sum > 0.0f) ? rot2_sum / fmaxf(mask_sum, 1.0f) : 0.0f;
        float recon = recon_total / (float)n_recon_elems;
        float tran = tran_sum / (float)(bs * 3);
        float size = size_sum / (float)(bs * 3);
        out[0] = 8.0f * rot1;
        out[1] = 8.0f * rot2;
        out[2] = 8.0f * recon;
        out[3] = 8.0f * tran;
        out[4] = 8.0f * size;
    }
}

extern "C" void kernel_launch(void* const* d_in, const int* in_sizes, int n_in,
                              void* d_out, int out_size) {
    const float* pred_Rot1  = (const float*)d_in[0];
    const float* pred_Rot2  = (const float*)d_in[1];
    const float* pred_Recon = (const float*)d_in[2];
    const float* pred_Tran  = (const float*)d_in[3];
    const float* pred_Size  = (const float*)d_in[4];
    const float* gt_Rot     = (const float*)d_in[5];
    const float* gt_Recon   = (const float*)d_in[6];
    const float* gt_Tran    = (const float*)d_in[7];
    const float* gt_Size    = (const float*)d_in[8];
    const int*   sym        = (const int*)d_in[9];
    float* out = (float*)d_out;

    const int n_recon = in_sizes[2];          // BS * N_PTS * 3
    const int bs      = in_sizes[0] / 3;      // batch size
    const int n4      = n_recon / 4;
    const int ntail   = n_recon - n4 * 4;

    int nblocks = (n4 + RTHR - 1) / RTHR;
    if (nblocks > RBLK_MAX) nblocks = RBLK_MAX;
    if (nblocks < 1) nblocks = 1;

    recon_reduce_kernel<<<nblocks, RTHR>>>(pred_Recon, gt_Recon, n4, ntail, nblocks);
    finalize_kernel<<<1, FTHR>>>(pred_Rot1, pred_Rot2, pred_Tran, pred_Size,
                                 gt_Rot, gt_Tran, gt_Size, sym, out,
                                 bs, n_recon, nblocks);
}